// round 4
// baseline (speedup 1.0000x reference)
#include <cuda_runtime.h>
#include <cstdint>
#include <math.h>

// LinearFullyConnectedGPLayer: MVLinear(left/right) -> Cl(3,0) geometric
// product -> MVLinear(out) -> MVLayerNorm. TF32 tensor-core GEMMs, fp32 GP.

namespace {
constexpr int C  = 512;    // Cin = Ch = Cout
constexpr int NB = 8;      // blades
constexpr int MAXB = 16384;

constexpr int TB = 8;      // batches per CTA (rows = 64)
constexpr int TN = 64;     // channels per CTA
constexpr int KC = 16;     // K per pipeline stage
constexpr int NSTAGE = C / KC;   // 32
constexpr int NTILE = C / TN;    // 8
}

// Scratch (device globals: no allocation allowed)
__device__ float g_gp[(size_t)MAXB * C * NB];
__device__ float g_normp[(size_t)MAXB * NTILE];
__device__ float g_scale[MAXB];

__device__ __forceinline__ uint32_t f2tf(float x) {
    uint32_t r;
    asm("cvt.rna.tf32.f32 %0, %1;" : "=r"(r) : "f"(x));
    return r;
}

__device__ __forceinline__ void mma8(float (&c)[4], const uint32_t (&a)[4],
                                     uint32_t b0, uint32_t b1) {
    asm volatile(
        "mma.sync.aligned.m16n8k8.row.col.f32.tf32.tf32.f32 "
        "{%0,%1,%2,%3}, {%4,%5,%6,%7}, {%8,%9}, {%0,%1,%2,%3};"
        : "+f"(c[0]), "+f"(c[1]), "+f"(c[2]), "+f"(c[3])
        : "r"(a[0]), "r"(a[1]), "r"(a[2]), "r"(a[3]), "r"(b0), "r"(b1));
}

// ============================================================================
// K1: left = vec1 @ WL^T, right = vec1 @ WR^T (bias on blade0), gp -> g_gp
// Grid (B/TB, C/TN), 128 threads, 2x2 warp grid of 32x32 warp tiles.
// ============================================================================
struct K1Pipe { uint32_t A[2][64][20]; uint32_t L[2][64][20]; uint32_t R[2][64][20]; };
struct K1Epi  { float L[64][65]; float R[64][65]; };
union  K1Smem { K1Pipe p; K1Epi e; };

__global__ void __launch_bounds__(128) k_gp(
    const float* __restrict__ vec1,
    const float* __restrict__ WL, const float* __restrict__ bLp,
    const float* __restrict__ WR, const float* __restrict__ bRp)
{
    __shared__ __align__(16) K1Smem sm;

    const int t = threadIdx.x;
    const int warp = t >> 5, lane = t & 31;
    const int b0 = blockIdx.x * TB;
    const int n0 = blockIdx.y * TN;

    float accL[2][4][4], accR[2][4][4];
#pragma unroll
    for (int i = 0; i < 2; ++i)
#pragma unroll
        for (int j = 0; j < 4; ++j)
#pragma unroll
            for (int k = 0; k < 4; ++k) { accL[i][j][k] = 0.f; accR[i][j][k] = 0.f; }

    const int a_bl = t >> 4;   // local batch 0..7
    const int a_k  = t & 15;   // k-in-stage 0..15
    const float* aptr = vec1 + ((size_t)(b0 + a_bl) * C + a_k) * NB;

    float pa[8], pl[8], pr[8];

    auto issue = [&](int s) {
        const float* ap = aptr + (size_t)s * KC * NB;
        float4 v0 = *reinterpret_cast<const float4*>(ap);
        float4 v1 = *reinterpret_cast<const float4*>(ap + 4);
        pa[0]=v0.x; pa[1]=v0.y; pa[2]=v0.z; pa[3]=v0.w;
        pa[4]=v1.x; pa[5]=v1.y; pa[6]=v1.z; pa[7]=v1.w;
        const int m0 = s * KC;
#pragma unroll
        for (int q2 = 0; q2 < 2; ++q2) {
            int q = t + q2 * 128;
            int n = q >> 2, k4 = (q & 3) * 4;
            float4 wl = *reinterpret_cast<const float4*>(WL + (size_t)(n0 + n) * C + m0 + k4);
            float4 wr = *reinterpret_cast<const float4*>(WR + (size_t)(n0 + n) * C + m0 + k4);
            pl[q2*4+0]=wl.x; pl[q2*4+1]=wl.y; pl[q2*4+2]=wl.z; pl[q2*4+3]=wl.w;
            pr[q2*4+0]=wr.x; pr[q2*4+1]=wr.y; pr[q2*4+2]=wr.z; pr[q2*4+3]=wr.w;
        }
    };

    auto commit = [&](int buf) {
#pragma unroll
        for (int i = 0; i < 8; ++i)
            sm.p.A[buf][a_bl * 8 + i][a_k] = f2tf(pa[i]);
#pragma unroll
        for (int q2 = 0; q2 < 2; ++q2) {
            int q = t + q2 * 128;
            int n = q >> 2, k4 = (q & 3) * 4;
            *reinterpret_cast<uint4*>(&sm.p.L[buf][n][k4]) =
                make_uint4(f2tf(pl[q2*4+0]), f2tf(pl[q2*4+1]), f2tf(pl[q2*4+2]), f2tf(pl[q2*4+3]));
            *reinterpret_cast<uint4*>(&sm.p.R[buf][n][k4]) =
                make_uint4(f2tf(pr[q2*4+0]), f2tf(pr[q2*4+1]), f2tf(pr[q2*4+2]), f2tf(pr[q2*4+3]));
        }
    };

    auto compute = [&](int buf) {
        const int rb = (warp >> 1) * 32;
        const int cb = (warp & 1) * 32;
#pragma unroll
        for (int kk = 0; kk < KC; kk += 8) {
            uint32_t a[2][4];
            const int ar = rb + (lane >> 2);
            const int ac = kk + (lane & 3);
#pragma unroll
            for (int rf = 0; rf < 2; ++rf) {
                a[rf][0] = sm.p.A[buf][ar + rf*16    ][ac];
                a[rf][1] = sm.p.A[buf][ar + rf*16 + 8][ac];
                a[rf][2] = sm.p.A[buf][ar + rf*16    ][ac + 4];
                a[rf][3] = sm.p.A[buf][ar + rf*16 + 8][ac + 4];
            }
#pragma unroll
            for (int cf = 0; cf < 4; ++cf) {
                const int bn = cb + cf * 8 + (lane >> 2);
                const int bk = kk + (lane & 3);
                uint32_t l0 = sm.p.L[buf][bn][bk], l1 = sm.p.L[buf][bn][bk + 4];
                uint32_t r0 = sm.p.R[buf][bn][bk], r1 = sm.p.R[buf][bn][bk + 4];
                mma8(accL[0][cf], a[0], l0, l1);
                mma8(accL[1][cf], a[1], l0, l1);
                mma8(accR[0][cf], a[0], r0, r1);
                mma8(accR[1][cf], a[1], r0, r1);
            }
        }
    };

    issue(0); commit(0);
    __syncthreads();
#pragma unroll 1
    for (int s = 0; s < NSTAGE; ++s) {
        const int buf = s & 1;
        if (s + 1 < NSTAGE) issue(s + 1);
        compute(buf);
        if (s + 1 < NSTAGE) commit(buf ^ 1);
        __syncthreads();
    }

    // accumulators -> smem
    {
        const int rb = (warp >> 1) * 32;
        const int cb = (warp & 1) * 32;
#pragma unroll
        for (int rf = 0; rf < 2; ++rf)
#pragma unroll
            for (int cf = 0; cf < 4; ++cf) {
                const int r = rb + rf * 16 + (lane >> 2);
                const int c = cb + cf * 8 + (lane & 3) * 2;
                sm.e.L[r    ][c]     = accL[rf][cf][0];
                sm.e.L[r    ][c + 1] = accL[rf][cf][1];
                sm.e.L[r + 8][c]     = accL[rf][cf][2];
                sm.e.L[r + 8][c + 1] = accL[rf][cf][3];
                sm.e.R[r    ][c]     = accR[rf][cf][0];
                sm.e.R[r    ][c + 1] = accR[rf][cf][1];
                sm.e.R[r + 8][c]     = accR[rf][cf][2];
                sm.e.R[r + 8][c + 1] = accR[rf][cf][3];
            }
    }
    __syncthreads();

    // Geometric product (Cl(3,0)) + store to g_gp
#pragma unroll
    for (int pp = 0; pp < 4; ++pp) {
        const int p = t + 128 * pp;
        const int bl = p >> 6, n = p & 63;
        float L[8], R[8];
#pragma unroll
        for (int i = 0; i < 8; ++i) { L[i] = sm.e.L[bl*8+i][n]; R[i] = sm.e.R[bl*8+i][n]; }
        L[0] += bLp[n0 + n];
        R[0] += bRp[n0 + n];
        float g0 = L[0]*R[0] + L[1]*R[1] + L[2]*R[2] + L[3]*R[3] - L[4]*R[4] - L[5]*R[5] - L[6]*R[6] - L[7]*R[7];
        float g1 = L[1]*R[0] + L[0]*R[1] - L[2]*R[4] - L[3]*R[5] + L[4]*R[2] + L[5]*R[3] - L[6]*R[7] - L[7]*R[6];
        float g2 = L[0]*R[2] + L[2]*R[0] + L[1]*R[4] - L[4]*R[1] - L[3]*R[6] + L[6]*R[3] + L[5]*R[7] + L[7]*R[5];
        float g3 = L[0]*R[3] + L[3]*R[0] + L[1]*R[5] - L[5]*R[1] + L[2]*R[6] - L[6]*R[2] - L[4]*R[7] - L[7]*R[4];
        float g4 = L[0]*R[4] + L[4]*R[0] + L[1]*R[2] - L[2]*R[1] + L[3]*R[7] + L[7]*R[3] - L[5]*R[6] + L[6]*R[5];
        float g5 = L[0]*R[5] + L[5]*R[0] + L[1]*R[3] - L[3]*R[1] - L[2]*R[7] - L[7]*R[2] + L[4]*R[6] - L[6]*R[4];
        float g6 = L[0]*R[6] + L[6]*R[0] + L[2]*R[3] - L[3]*R[2] + L[1]*R[7] + L[7]*R[1] - L[4]*R[5] + L[5]*R[4];
        float g7 = L[0]*R[7] + L[7]*R[0] + L[1]*R[6] + L[6]*R[1] - L[2]*R[5] - L[5]*R[2] + L[3]*R[4] + L[4]*R[3];
        float* dst = g_gp + ((size_t)(b0 + bl) * C + n0 + n) * NB;
        *reinterpret_cast<float4*>(dst)     = make_float4(g0, g1, g2, g3);
        *reinterpret_cast<float4*>(dst + 4) = make_float4(g4, g5, g6, g7);
    }
}

// ============================================================================
// K2: out = gp @ WO^T (+bO blade0), write raw out, norm partials -> g_normp
// ============================================================================
struct K2Pipe { uint32_t A[2][64][20]; uint32_t B[2][64][20]; };
struct K2Epi  { float O[64][65]; };
union  K2Smem { K2Pipe p; K2Epi e; };

__global__ void __launch_bounds__(128) k_out(
    const float* __restrict__ WO, const float* __restrict__ bOp,
    float* __restrict__ outp)
{
    __shared__ __align__(16) K2Smem sm;

    const int t = threadIdx.x;
    const int warp = t >> 5, lane = t & 31;
    const int b0 = blockIdx.x * TB;
    const int n0 = blockIdx.y * TN;

    float accO[2][4][4];
#pragma unroll
    for (int i = 0; i < 2; ++i)
#pragma unroll
        for (int j = 0; j < 4; ++j)
#pragma unroll
            for (int k = 0; k < 4; ++k) accO[i][j][k] = 0.f;

    const int a_bl = t >> 4;
    const int a_k  = t & 15;
    const float* aptr = g_gp + ((size_t)(b0 + a_bl) * C + a_k) * NB;

    float pa[8], pw[8];

    auto issue = [&](int s) {
        const float* ap = aptr + (size_t)s * KC * NB;
        float4 v0 = *reinterpret_cast<const float4*>(ap);
        float4 v1 = *reinterpret_cast<const float4*>(ap + 4);
        pa[0]=v0.x; pa[1]=v0.y; pa[2]=v0.z; pa[3]=v0.w;
        pa[4]=v1.x; pa[5]=v1.y; pa[6]=v1.z; pa[7]=v1.w;
        const int m0 = s * KC;
#pragma unroll
        for (int q2 = 0; q2 < 2; ++q2) {
            int q = t + q2 * 128;
            int n = q >> 2, k4 = (q & 3) * 4;
            float4 w = *reinterpret_cast<const float4*>(WO + (size_t)(n0 + n) * C + m0 + k4);
            pw[q2*4+0]=w.x; pw[q2*4+1]=w.y; pw[q2*4+2]=w.z; pw[q2*4+3]=w.w;
        }
    };

    auto commit = [&](int buf) {
#pragma unroll
        for (int i = 0; i < 8; ++i)
            sm.p.A[buf][a_bl * 8 + i][a_k] = f2tf(pa[i]);
#pragma unroll
        for (int q2 = 0; q2 < 2; ++q2) {
            int q = t + q2 * 128;
            int n = q >> 2, k4 = (q & 3) * 4;
            *reinterpret_cast<uint4*>(&sm.p.B[buf][n][k4]) =
                make_uint4(f2tf(pw[q2*4+0]), f2tf(pw[q2*4+1]), f2tf(pw[q2*4+2]), f2tf(pw[q2*4+3]));
        }
    };

    auto compute = [&](int buf) {
        const int rb = (warp >> 1) * 32;
        const int cb = (warp & 1) * 32;
#pragma unroll
        for (int kk = 0; kk < KC; kk += 8) {
            uint32_t a[2][4];
            const int ar = rb + (lane >> 2);
            const int ac = kk + (lane & 3);
#pragma unroll
            for (int rf = 0; rf < 2; ++rf) {
                a[rf][0] = sm.p.A[buf][ar + rf*16    ][ac];
                a[rf][1] = sm.p.A[buf][ar + rf*16 + 8][ac];
                a[rf][2] = sm.p.A[buf][ar + rf*16    ][ac + 4];
                a[rf][3] = sm.p.A[buf][ar + rf*16 + 8][ac + 4];
            }
#pragma unroll
            for (int cf = 0; cf < 4; ++cf) {
                const int bn = cb + cf * 8 + (lane >> 2);
                const int bk = kk + (lane & 3);
                uint32_t w0 = sm.p.B[buf][bn][bk], w1 = sm.p.B[buf][bn][bk + 4];
                mma8(accO[0][cf], a[0], w0, w1);
                mma8(accO[1][cf], a[1], w0, w1);
            }
        }
    };

    issue(0); commit(0);
    __syncthreads();
#pragma unroll 1
    for (int s = 0; s < NSTAGE; ++s) {
        const int buf = s & 1;
        if (s + 1 < NSTAGE) issue(s + 1);
        compute(buf);
        if (s + 1 < NSTAGE) commit(buf ^ 1);
        __syncthreads();
    }

    {
        const int rb = (warp >> 1) * 32;
        const int cb = (warp & 1) * 32;
#pragma unroll
        for (int rf = 0; rf < 2; ++rf)
#pragma unroll
            for (int cf = 0; cf < 4; ++cf) {
                const int r = rb + rf * 16 + (lane >> 2);
                const int c = cb + cf * 8 + (lane & 3) * 2;
                sm.e.O[r    ][c]     = accO[rf][cf][0];
                sm.e.O[r    ][c + 1] = accO[rf][cf][1];
                sm.e.O[r + 8][c]     = accO[rf][cf][2];
                sm.e.O[r + 8][c + 1] = accO[rf][cf][3];
            }
    }
    __syncthreads();

    const int bl = t >> 4;       // local batch; 16 lanes per batch
    const int cbase = t & 15;
    float psum = 0.f;
#pragma unroll
    for (int pp = 0; pp < 4; ++pp) {
        const int c = cbase + 16 * pp;
        float o[8];
#pragma unroll
        for (int i = 0; i < 8; ++i) o[i] = sm.e.O[bl*8+i][c];
        o[0] += bOp[n0 + c];
        float ss = 0.f;
#pragma unroll
        for (int i = 0; i < 8; ++i) ss += o[i] * o[i];
        psum += sqrtf(ss);
        float* dst = outp + ((size_t)(b0 + bl) * C + n0 + c) * NB;
        *reinterpret_cast<float4*>(dst)     = make_float4(o[0], o[1], o[2], o[3]);
        *reinterpret_cast<float4*>(dst + 4) = make_float4(o[4], o[5], o[6], o[7]);
    }
#pragma unroll
    for (int off = 8; off > 0; off >>= 1)
        psum += __shfl_down_sync(0xffffffffu, psum, off);
    if ((lane & 15) == 0)
        g_normp[(size_t)(b0 + bl) * NTILE + blockIdx.y] = psum;
}

// ============================================================================
__global__ void __launch_bounds__(256) k_red(int B) {
    const int b = blockIdx.x * 256 + threadIdx.x;
    if (b < B) {
        float s = 0.f;
#pragma unroll
        for (int j = 0; j < NTILE; ++j) s += g_normp[(size_t)b * NTILE + j];
        g_scale[b] = 1.f / (s * (1.f / (float)C) + 1e-6f);
    }
}

__global__ void __launch_bounds__(256) k_scale(float* __restrict__ outp,
                                               const float* __restrict__ an) {
    const size_t idx = (size_t)blockIdx.x * 256 + threadIdx.x;  // float4 index
    const int b = (int)(idx >> 10);           // 1024 float4 per batch
    const int c = ((int)idx >> 1) & (C - 1);  // 2 float4 per channel
    const float s = an[c] * g_scale[b];
    float4* o4 = reinterpret_cast<float4*>(outp) + idx;
    float4 v = *o4;
    v.x *= s; v.y *= s; v.z *= s; v.w *= s;
    *o4 = v;
}

// ============================================================================
extern "C" void kernel_launch(void* const* d_in, const int* in_sizes, int n_in,
                              void* d_out, int out_size) {
    const float* vec1 = (const float*)d_in[0];
    const float* WL   = (const float*)d_in[1];
    const float* bL   = (const float*)d_in[2];
    const float* WR   = (const float*)d_in[3];
    const float* bR   = (const float*)d_in[4];
    const float* WO   = (const float*)d_in[5];
    const float* bO   = (const float*)d_in[6];
    const float* an   = (const float*)d_in[7];
    float* out = (float*)d_out;

    int B = in_sizes[0] / (C * NB);   // 16384
    if (B > MAXB) B = MAXB;

    dim3 g1(B / TB, C / TN);
    k_gp<<<g1, 128>>>(vec1, WL, bL, WR, bR);
    k_out<<<g1, 128>>>(WO, bO, out);
    k_red<<<(B + 255) / 256, 256>>>(B);
    const size_t nvec4 = (size_t)B * C * NB / 4;
    k_scale<<<(unsigned)(nvec4 / 256), 256>>>(out, an);
}

// round 6
// speedup vs baseline: 1.5906x; 1.5906x over previous
#include <cuda_runtime.h>
#include <cstdint>
#include <math.h>

// LinearFullyConnectedGPLayer on sm_100 (legacy mma.sync path; tcgen05 is not
// available under the harness's -arch=sm_100 target):
//   k_wround : tf32-RNA round the three weights into device globals
//   k_tr     : transpose vec1 (b,m,i) -> row-major [(b*8+i)][m], tf32-RNA
//   k1       : L = A@WL^T, R = A@WR^T via mma.sync.tf32 (cp.async pipeline),
//              epilogue: bias + Cl(3,0) geometric product -> g_gp (tf32)
//   k2       : O = gp@WO^T, epilogue: bias, store out (b,n,i), norm partials
//   k_red    : per-batch scale
//   k_scale  : out *= a_norm[c] / (mean_norm + eps)

namespace {
constexpr int C    = 512;
constexpr int NB   = 8;
constexpr int MAXB = 16384;
constexpr int ROWS = MAXB * NB;

constexpr int TM   = 128;          // rows per CTA (16 batches x 8 blades)
constexpr int TN   = 64;           // channels per CTA
constexpr int KC   = 32;           // K per stage
constexpr int NIT  = C / KC;       // 16
constexpr int NTILE = C / TN;      // 8

constexpr int PIT  = 36;           // smem stage pitch (floats), conflict-free
// K1 stage layout (floats): A[128][36], WL[64][36], WR[64][36]
constexpr int ST_A  = 0;
constexpr int ST_WL = 128 * PIT;           // 4608
constexpr int ST_WR = ST_WL + 64 * PIT;    // 6912
constexpr int ST_SZ = ST_WR + 64 * PIT;    // 9216 floats
constexpr int K1_SMEM = 2 * ST_SZ * 4;     // 73728 B
// K2 stage layout: A[128][36], WO[64][36]
constexpr int K2_ST_SZ = (128 + 64) * PIT; // 6912 floats
constexpr int K2_SMEM  = 2 * K2_ST_SZ * 4; // 55296 B
constexpr int EPI_P = 68;                  // epilogue pitch
}

// ---- scratch (device globals; no allocation allowed) ----
__device__ float g_a [(size_t)ROWS * C];
__device__ float g_gp[(size_t)ROWS * C];
__device__ float g_wl[(size_t)C * C];
__device__ float g_wr[(size_t)C * C];
__device__ float g_wo[(size_t)C * C];
__device__ float g_normp[(size_t)MAXB * NTILE];
__device__ float g_scale[MAXB];

// ---- helpers ----
__device__ __forceinline__ uint32_t smem_u32(const void* p) {
    uint32_t a;
    asm("{ .reg .u64 t; cvta.to.shared.u64 t, %1; cvt.u32.u64 %0, t; }"
        : "=r"(a) : "l"(p));
    return a;
}
__device__ __forceinline__ float tfround(float x) {
    uint32_t r;
    asm("cvt.rna.tf32.f32 %0, %1;" : "=r"(r) : "f"(x));
    return __uint_as_float(r);
}
__device__ __forceinline__ void cp16(uint32_t dst, const void* src) {
    asm volatile("cp.async.cg.shared.global [%0], [%1], 16;"
                 :: "r"(dst), "l"(src) : "memory");
}
__device__ __forceinline__ void cp_commit() {
    asm volatile("cp.async.commit_group;" ::: "memory");
}
__device__ __forceinline__ void cp_wait1() {
    asm volatile("cp.async.wait_group 1;" ::: "memory");
}
__device__ __forceinline__ void cp_wait0() {
    asm volatile("cp.async.wait_group 0;" ::: "memory");
}
__device__ __forceinline__ void mma8(float (&c)[4], const uint32_t (&a)[4],
                                     uint32_t b0, uint32_t b1) {
    asm volatile(
        "mma.sync.aligned.m16n8k8.row.col.f32.tf32.tf32.f32 "
        "{%0,%1,%2,%3}, {%4,%5,%6,%7}, {%8,%9}, {%0,%1,%2,%3};"
        : "+f"(c[0]), "+f"(c[1]), "+f"(c[2]), "+f"(c[3])
        : "r"(a[0]), "r"(a[1]), "r"(a[2]), "r"(a[3]), "r"(b0), "r"(b1));
}

// ============================================================================
// k_wround: tf32-RNA round weights into g_wl/g_wr/g_wo
// ============================================================================
__global__ void __launch_bounds__(256) k_wround(
    const float* __restrict__ WL, const float* __restrict__ WR,
    const float* __restrict__ WO)
{
    const int q = blockIdx.x * 256 + threadIdx.x;   // float4 index, 196608
    const int e = q * 4;
    const float* src;
    float* dst;
    if (e < 262144)       { src = WL + e;          dst = g_wl + e; }
    else if (e < 524288)  { src = WR + e - 262144; dst = g_wr + e - 262144; }
    else                  { src = WO + e - 524288; dst = g_wo + e - 524288; }
    float4 v = *reinterpret_cast<const float4*>(src);
    v.x = tfround(v.x); v.y = tfround(v.y); v.z = tfround(v.z); v.w = tfround(v.w);
    *reinterpret_cast<float4*>(dst) = v;
}

// ============================================================================
// k_tr: g_a[(b*8+i)*512 + m] = tf32(vec1[(b*512+m)*8 + i]); one batch per CTA
// ============================================================================
__global__ void __launch_bounds__(256) k_tr(const float* __restrict__ vec1) {
    __shared__ float smT[8][516];
    const int b = blockIdx.x;
    const int t = threadIdx.x;
    const float* src = vec1 + (size_t)b * C * NB;
#pragma unroll
    for (int u = 0; u < 4; ++u) {
        int q = t + 256 * u;             // float4 index 0..1023
        int m = q >> 1, ih = q & 1;
        float4 v = *reinterpret_cast<const float4*>(src + (size_t)m * 8 + ih * 4);
        smT[ih * 4 + 0][m] = v.x;
        smT[ih * 4 + 1][m] = v.y;
        smT[ih * 4 + 2][m] = v.z;
        smT[ih * 4 + 3][m] = v.w;
    }
    __syncthreads();
    float* dst = g_a + (size_t)b * NB * C;
#pragma unroll
    for (int u = 0; u < 4; ++u) {
        int q = t + 256 * u;
        int i = q >> 7, mf = q & 127;
        float4 v = *reinterpret_cast<const float4*>(&smT[i][mf * 4]);
        v.x = tfround(v.x); v.y = tfround(v.y); v.z = tfround(v.z); v.w = tfround(v.w);
        *reinterpret_cast<float4*>(dst + (size_t)i * C + mf * 4) = v;
    }
}

// ============================================================================
// k1: L/R GEMMs (shared A) + bias + geometric product -> g_gp
// grid (B/16, 8), 256 threads; 8 warps in 4x2, warp tile 32x32
// ============================================================================
__global__ void __launch_bounds__(256) k1(
    const float* __restrict__ bLp, const float* __restrict__ bRp)
{
    extern __shared__ float s[];
    const uint32_t sb = smem_u32(s);
    const int t = threadIdx.x;
    const int warp = t >> 5, lane = t & 31;
    const int wm = warp >> 1, wn = warp & 1;
    const int b0r = blockIdx.x * TM;
    const int n0  = blockIdx.y * TN;

    float accL[2][4][4] = {}, accR[2][4][4] = {};

    auto load_stage = [&](int st) {
        const uint32_t base = sb + (uint32_t)((st & 1) * ST_SZ * 4);
        const int k0 = st * KC;
#pragma unroll
        for (int u = 0; u < 4; ++u) {                   // A: 1024 chunks
            int idx = t + 256 * u;
            int row = idx >> 3, c4 = idx & 7;
            cp16(base + (uint32_t)((ST_A + row * PIT + c4 * 4) * 4),
                 g_a + (size_t)(b0r + row) * C + k0 + c4 * 4);
        }
#pragma unroll
        for (int u = 0; u < 2; ++u) {                   // WL/WR: 512 each
            int idx = t + 256 * u;
            int row = idx >> 3, c4 = idx & 7;
            cp16(base + (uint32_t)((ST_WL + row * PIT + c4 * 4) * 4),
                 g_wl + (size_t)(n0 + row) * C + k0 + c4 * 4);
            cp16(base + (uint32_t)((ST_WR + row * PIT + c4 * 4) * 4),
                 g_wr + (size_t)(n0 + row) * C + k0 + c4 * 4);
        }
        cp_commit();
    };

    auto compute = [&](int buf) {
        const float* base = s + buf * ST_SZ;
        const float* Ab = base + ST_A  + (wm * 32 + (lane >> 2)) * PIT + (lane & 3);
        const float* Lb = base + ST_WL + (wn * 32 + (lane >> 2)) * PIT + (lane & 3);
        const float* Rb = base + ST_WR + (wn * 32 + (lane >> 2)) * PIT + (lane & 3);
#pragma unroll
        for (int kk = 0; kk < KC; kk += 8) {
            uint32_t a[2][4];
#pragma unroll
            for (int rf = 0; rf < 2; ++rf) {
                const float* ap = Ab + rf * 16 * PIT + kk;
                a[rf][0] = __float_as_uint(ap[0]);
                a[rf][1] = __float_as_uint(ap[8 * PIT]);
                a[rf][2] = __float_as_uint(ap[4]);
                a[rf][3] = __float_as_uint(ap[8 * PIT + 4]);
            }
#pragma unroll
            for (int cf = 0; cf < 4; ++cf) {
                const float* lp = Lb + cf * 8 * PIT + kk;
                const float* rp = Rb + cf * 8 * PIT + kk;
                uint32_t l0 = __float_as_uint(lp[0]), l1 = __float_as_uint(lp[4]);
                uint32_t r0 = __float_as_uint(rp[0]), r1 = __float_as_uint(rp[4]);
                mma8(accL[0][cf], a[0], l0, l1);
                mma8(accL[1][cf], a[1], l0, l1);
                mma8(accR[0][cf], a[0], r0, r1);
                mma8(accR[1][cf], a[1], r0, r1);
            }
        }
    };

    load_stage(0);
    load_stage(1);
#pragma unroll 1
    for (int it = 0; it < NIT; ++it) {
        const int buf = it & 1;
        if (it >= NIT - 2) cp_wait0(); else cp_wait1();
        __syncthreads();
        compute(buf);
        __syncthreads();
        if (it + 2 < NIT) load_stage(it + 2);
    }

    // epilogue: accumulators -> smem [128][EPI_P] x2 (reuses pipe smem)
    float* Ls = s;
    float* Rs = s + 128 * EPI_P;
#pragma unroll
    for (int rf = 0; rf < 2; ++rf)
#pragma unroll
        for (int cf = 0; cf < 4; ++cf) {
            const int r = wm * 32 + rf * 16 + (lane >> 2);
            const int c = wn * 32 + cf * 8 + 2 * (lane & 3);
            Ls[r * EPI_P + c]           = accL[rf][cf][0];
            Ls[r * EPI_P + c + 1]       = accL[rf][cf][1];
            Ls[(r + 8) * EPI_P + c]     = accL[rf][cf][2];
            Ls[(r + 8) * EPI_P + c + 1] = accL[rf][cf][3];
            Rs[r * EPI_P + c]           = accR[rf][cf][0];
            Rs[r * EPI_P + c + 1]       = accR[rf][cf][1];
            Rs[(r + 8) * EPI_P + c]     = accR[rf][cf][2];
            Rs[(r + 8) * EPI_P + c + 1] = accR[rf][cf][3];
        }
    __syncthreads();

    // bias + geometric product (Cl(3,0)) + tf32 round -> g_gp
#pragma unroll
    for (int j = 0; j < 4; ++j) {
        const int p = t + 256 * j;          // 1024 (b,c) pairs
        const int b = p >> 6, c = p & 63;
        float L[8], R[8];
#pragma unroll
        for (int i = 0; i < 8; ++i) {
            L[i] = Ls[(b * 8 + i) * EPI_P + c];
            R[i] = Rs[(b * 8 + i) * EPI_P + c];
        }
        L[0] += bLp[n0 + c];
        R[0] += bRp[n0 + c];
        float g[8];
        g[0] = L[0]*R[0] + L[1]*R[1] + L[2]*R[2] + L[3]*R[3] - L[4]*R[4] - L[5]*R[5] - L[6]*R[6] - L[7]*R[7];
        g[1] = L[1]*R[0] + L[0]*R[1] - L[2]*R[4] - L[3]*R[5] + L[4]*R[2] + L[5]*R[3] - L[6]*R[7] - L[7]*R[6];
        g[2] = L[0]*R[2] + L[2]*R[0] + L[1]*R[4] - L[4]*R[1] - L[3]*R[6] + L[6]*R[3] + L[5]*R[7] + L[7]*R[5];
        g[3] = L[0]*R[3] + L[3]*R[0] + L[1]*R[5] - L[5]*R[1] + L[2]*R[6] - L[6]*R[2] - L[4]*R[7] - L[7]*R[4];
        g[4] = L[0]*R[4] + L[4]*R[0] + L[1]*R[2] - L[2]*R[1] + L[3]*R[7] + L[7]*R[3] - L[5]*R[6] + L[6]*R[5];
        g[5] = L[0]*R[5] + L[5]*R[0] + L[1]*R[3] - L[3]*R[1] - L[2]*R[7] - L[7]*R[2] + L[4]*R[6] - L[6]*R[4];
        g[6] = L[0]*R[6] + L[6]*R[0] + L[2]*R[3] - L[3]*R[2] + L[1]*R[7] + L[7]*R[1] - L[4]*R[5] + L[5]*R[4];
        g[7] = L[0]*R[7] + L[7]*R[0] + L[1]*R[6] + L[6]*R[1] - L[2]*R[5] - L[5]*R[2] + L[3]*R[4] + L[4]*R[3];
#pragma unroll
        for (int i = 0; i < 8; ++i)
            g_gp[(size_t)(b0r + b * 8 + i) * C + n0 + c] = tfround(g[i]);
    }
}

// ============================================================================
// k2: O = gp @ WO^T + bias; store out (b,n,i); norm partials
// ============================================================================
__global__ void __launch_bounds__(256) k2(
    const float* __restrict__ bOp, float* __restrict__ outp)
{
    extern __shared__ float s[];
    const uint32_t sb = smem_u32(s);
    const int t = threadIdx.x;
    const int warp = t >> 5, lane = t & 31;
    const int wm = warp >> 1, wn = warp & 1;
    const int b0r = blockIdx.x * TM;
    const int b0b = blockIdx.x * 16;
    const int n0  = blockIdx.y * TN;

    float acc[2][4][4] = {};

    auto load_stage = [&](int st) {
        const uint32_t base = sb + (uint32_t)((st & 1) * K2_ST_SZ * 4);
        const int k0 = st * KC;
#pragma unroll
        for (int u = 0; u < 4; ++u) {
            int idx = t + 256 * u;
            int row = idx >> 3, c4 = idx & 7;
            cp16(base + (uint32_t)((ST_A + row * PIT + c4 * 4) * 4),
                 g_gp + (size_t)(b0r + row) * C + k0 + c4 * 4);
        }
#pragma unroll
        for (int u = 0; u < 2; ++u) {
            int idx = t + 256 * u;
            int row = idx >> 3, c4 = idx & 7;
            cp16(base + (uint32_t)((ST_WL + row * PIT + c4 * 4) * 4),
                 g_wo + (size_t)(n0 + row) * C + k0 + c4 * 4);
        }
        cp_commit();
    };

    auto compute = [&](int buf) {
        const float* base = s + buf * K2_ST_SZ;
        const float* Ab = base + ST_A  + (wm * 32 + (lane >> 2)) * PIT + (lane & 3);
        const float* Wb = base + ST_WL + (wn * 32 + (lane >> 2)) * PIT + (lane & 3);
#pragma unroll
        for (int kk = 0; kk < KC; kk += 8) {
            uint32_t a[2][4];
#pragma unroll
            for (int rf = 0; rf < 2; ++rf) {
                const float* ap = Ab + rf * 16 * PIT + kk;
                a[rf][0] = __float_as_uint(ap[0]);
                a[rf][1] = __float_as_uint(ap[8 * PIT]);
                a[rf][2] = __float_as_uint(ap[4]);
                a[rf][3] = __float_as_uint(ap[8 * PIT + 4]);
            }
#pragma unroll
            for (int cf = 0; cf < 4; ++cf) {
                const float* wp = Wb + cf * 8 * PIT + kk;
                uint32_t w0 = __float_as_uint(wp[0]), w1 = __float_as_uint(wp[4]);
                mma8(acc[0][cf], a[0], w0, w1);
                mma8(acc[1][cf], a[1], w0, w1);
            }
        }
    };

    load_stage(0);
    load_stage(1);
#pragma unroll 1
    for (int it = 0; it < NIT; ++it) {
        const int buf = it & 1;
        if (it >= NIT - 2) cp_wait0(); else cp_wait1();
        __syncthreads();
        compute(buf);
        __syncthreads();
        if (it + 2 < NIT) load_stage(it + 2);
    }

    float* Os = s;                    // [128][EPI_P]
    float* Ns = s + 128 * EPI_P;      // [16][64]
#pragma unroll
    for (int rf = 0; rf < 2; ++rf)
#pragma unroll
        for (int cf = 0; cf < 4; ++cf) {
            const int r = wm * 32 + rf * 16 + (lane >> 2);
            const int c = wn * 32 + cf * 8 + 2 * (lane & 3);
            Os[r * EPI_P + c]           = acc[rf][cf][0];
            Os[r * EPI_P + c + 1]       = acc[rf][cf][1];
            Os[(r + 8) * EPI_P + c]     = acc[rf][cf][2];
            Os[(r + 8) * EPI_P + c + 1] = acc[rf][cf][3];
        }
    __syncthreads();

#pragma unroll
    for (int j = 0; j < 4; ++j) {
        const int p = t + 256 * j;
        const int b = p >> 6, c = p & 63;
        const int nc = n0 + c;
        float o[8];
#pragma unroll
        for (int i = 0; i < 8; ++i) o[i] = Os[(b * 8 + i) * EPI_P + c];
        o[0] += bOp[nc];
        float ss = 0.f;
#pragma unroll
        for (int i = 0; i < 8; ++i) ss += o[i] * o[i];
        Ns[b * 64 + c] = sqrtf(ss);
        float* dst = outp + ((size_t)(b0b + b) * C + nc) * NB;
        *reinterpret_cast<float4*>(dst)     = make_float4(o[0], o[1], o[2], o[3]);
        *reinterpret_cast<float4*>(dst + 4) = make_float4(o[4], o[5], o[6], o[7]);
    }
    __syncthreads();

    // norm reduce: warp w -> batches 2w, 2w+1
#pragma unroll
    for (int bb = 0; bb < 2; ++bb) {
        const int b = warp * 2 + bb;
        float v = Ns[b * 64 + lane] + Ns[b * 64 + lane + 32];
#pragma unroll
        for (int off = 16; off > 0; off >>= 1)
            v += __shfl_down_sync(0xffffffffu, v, off);
        if (lane == 0)
            g_normp[(size_t)(b0b + b) * NTILE + blockIdx.y] = v;
    }
}

// ============================================================================
__global__ void __launch_bounds__(256) k_red(int B) {
    const int b = blockIdx.x * 256 + threadIdx.x;
    if (b < B) {
        float v = 0.f;
#pragma unroll
        for (int j = 0; j < NTILE; ++j) v += g_normp[(size_t)b * NTILE + j];
        g_scale[b] = 1.f / (v * (1.f / (float)C) + 1e-6f);
    }
}

__global__ void __launch_bounds__(256) k_scale(float* __restrict__ outp,
                                               const float* __restrict__ an) {
    const size_t idx = (size_t)blockIdx.x * 256 + threadIdx.x;  // float4 index
    const int b = (int)(idx >> 10);
    const int c = ((int)idx >> 1) & (C - 1);
    const float v = an[c] * g_scale[b];
    float4* o4 = reinterpret_cast<float4*>(outp) + idx;
    float4 w = *o4;
    w.x *= v; w.y *= v; w.z *= v; w.w *= v;
    *o4 = w;
}

// ============================================================================
extern "C" void kernel_launch(void* const* d_in, const int* in_sizes, int n_in,
                              void* d_out, int out_size) {
    const float* vec1 = (const float*)d_in[0];
    const float* WL   = (const float*)d_in[1];
    const float* bL   = (const float*)d_in[2];
    const float* WR   = (const float*)d_in[3];
    const float* bR   = (const float*)d_in[4];
    const float* WO   = (const float*)d_in[5];
    const float* bO   = (const float*)d_in[6];
    const float* an   = (const float*)d_in[7];
    float* out = (float*)d_out;

    int B = in_sizes[0] / (C * NB);   // 16384
    if (B > MAXB) B = MAXB;

    cudaFuncSetAttribute(k1, cudaFuncAttributeMaxDynamicSharedMemorySize, K1_SMEM);
    cudaFuncSetAttribute(k2, cudaFuncAttributeMaxDynamicSharedMemorySize, K2_SMEM);

    k_wround<<<768, 256>>>(WL, WR, WO);
    k_tr<<<B, 256>>>(vec1);
    dim3 g(B / 16, NTILE);
    k1<<<g, 256, K1_SMEM>>>(bL, bR);
    k2<<<g, 256, K2_SMEM>>>(bO, out);
    k_red<<<(B + 255) / 256, 256>>>(B);
    k_scale<<<(unsigned)((size_t)B * 1024 / 256), 256>>>(out, an);
}

// round 8
// speedup vs baseline: 1.5925x; 1.0012x over previous
#include <cuda_runtime.h>
#include <cstdint>
#include <math.h>

// LinearFullyConnectedGPLayer on sm_100 (legacy mma.sync tf32 path).
// R7/R8 change vs R6: grid axes swapped so the n-tile dimension is blockIdx.x
// (fastest varying). Co-resident CTAs then share A row-tiles through L2,
// cutting A DRAM traffic 8x in both GEMM kernels.

namespace {
constexpr int C    = 512;
constexpr int NB   = 8;
constexpr int MAXB = 16384;
constexpr int ROWS = MAXB * NB;

constexpr int TM   = 128;          // rows per CTA (16 batches x 8 blades)
constexpr int TN   = 64;           // channels per CTA
constexpr int KC   = 32;           // K per stage
constexpr int NIT  = C / KC;       // 16
constexpr int NTILE = C / TN;      // 8

constexpr int PIT  = 36;           // smem stage pitch (floats), conflict-free
constexpr int ST_A  = 0;
constexpr int ST_WL = 128 * PIT;           // 4608
constexpr int ST_WR = ST_WL + 64 * PIT;    // 6912
constexpr int ST_SZ = ST_WR + 64 * PIT;    // 9216 floats
constexpr int K1_SMEM = 2 * ST_SZ * 4;     // 73728 B
constexpr int K2_ST_SZ = (128 + 64) * PIT; // 6912 floats
constexpr int K2_SMEM  = 2 * K2_ST_SZ * 4; // 55296 B
constexpr int EPI_P = 68;                  // epilogue pitch
}

// ---- scratch (device globals; no allocation allowed) ----
__device__ float g_a [(size_t)ROWS * C];
__device__ float g_gp[(size_t)ROWS * C];
__device__ float g_wl[(size_t)C * C];
__device__ float g_wr[(size_t)C * C];
__device__ float g_wo[(size_t)C * C];
__device__ float g_normp[(size_t)MAXB * NTILE];
__device__ float g_scale[MAXB];

// ---- helpers ----
__device__ __forceinline__ uint32_t smem_u32(const void* p) {
    uint32_t a;
    asm("{ .reg .u64 t; cvta.to.shared.u64 t, %1; cvt.u32.u64 %0, t; }"
        : "=r"(a) : "l"(p));
    return a;
}
__device__ __forceinline__ float tfround(float x) {
    uint32_t r;
    asm("cvt.rna.tf32.f32 %0, %1;" : "=r"(r) : "f"(x));
    return __uint_as_float(r);
}
__device__ __forceinline__ void cp16(uint32_t dst, const void* src) {
    asm volatile("cp.async.cg.shared.global [%0], [%1], 16;"
                 :: "r"(dst), "l"(src) : "memory");
}
__device__ __forceinline__ void cp_commit() {
    asm volatile("cp.async.commit_group;" ::: "memory");
}
__device__ __forceinline__ void cp_wait1() {
    asm volatile("cp.async.wait_group 1;" ::: "memory");
}
__device__ __forceinline__ void cp_wait0() {
    asm volatile("cp.async.wait_group 0;" ::: "memory");
}
__device__ __forceinline__ void mma8(float (&c)[4], const uint32_t (&a)[4],
                                     uint32_t b0, uint32_t b1) {
    asm volatile(
        "mma.sync.aligned.m16n8k8.row.col.f32.tf32.tf32.f32 "
        "{%0,%1,%2,%3}, {%4,%5,%6,%7}, {%8,%9}, {%0,%1,%2,%3};"
        : "+f"(c[0]), "+f"(c[1]), "+f"(c[2]), "+f"(c[3])
        : "r"(a[0]), "r"(a[1]), "r"(a[2]), "r"(a[3]), "r"(b0), "r"(b1));
}

// ============================================================================
// k_wround: tf32-RNA round weights into g_wl/g_wr/g_wo
// ============================================================================
__global__ void __launch_bounds__(256) k_wround(
    const float* __restrict__ WL, const float* __restrict__ WR,
    const float* __restrict__ WO)
{
    const int q = blockIdx.x * 256 + threadIdx.x;   // float4 index, 196608
    const int e = q * 4;
    const float* src;
    float* dst;
    if (e < 262144)       { src = WL + e;          dst = g_wl + e; }
    else if (e < 524288)  { src = WR + e - 262144; dst = g_wr + e - 262144; }
    else                  { src = WO + e - 524288; dst = g_wo + e - 524288; }
    float4 v = *reinterpret_cast<const float4*>(src);
    v.x = tfround(v.x); v.y = tfround(v.y); v.z = tfround(v.z); v.w = tfround(v.w);
    *reinterpret_cast<float4*>(dst) = v;
}

// ============================================================================
// k_tr: g_a[(b*8+i)*512 + m] = tf32(vec1[(b*512+m)*8 + i]); one batch per CTA
// ============================================================================
__global__ void __launch_bounds__(256) k_tr(const float* __restrict__ vec1) {
    __shared__ float smT[8][516];
    const int b = blockIdx.x;
    const int t = threadIdx.x;
    const float* src = vec1 + (size_t)b * C * NB;
#pragma unroll
    for (int u = 0; u < 4; ++u) {
        int q = t + 256 * u;             // float4 index 0..1023
        int m = q >> 1, ih = q & 1;
        float4 v = *reinterpret_cast<const float4*>(src + (size_t)m * 8 + ih * 4);
        smT[ih * 4 + 0][m] = v.x;
        smT[ih * 4 + 1][m] = v.y;
        smT[ih * 4 + 2][m] = v.z;
        smT[ih * 4 + 3][m] = v.w;
    }
    __syncthreads();
    float* dst = g_a + (size_t)b * NB * C;
#pragma unroll
    for (int u = 0; u < 4; ++u) {
        int q = t + 256 * u;
        int i = q >> 7, mf = q & 127;
        float4 v = *reinterpret_cast<const float4*>(&smT[i][mf * 4]);
        v.x = tfround(v.x); v.y = tfround(v.y); v.z = tfround(v.z); v.w = tfround(v.w);
        *reinterpret_cast<float4*>(dst + (size_t)i * C + mf * 4) = v;
    }
}

// ============================================================================
// k1: L/R GEMMs (shared A) + bias + geometric product -> g_gp
// grid (NTILE, B/16): x = n-tile (fast), y = row-tile. 256 thr, 4x2 warps.
// ============================================================================
__global__ void __launch_bounds__(256) k1(
    const float* __restrict__ bLp, const float* __restrict__ bRp)
{
    extern __shared__ float s[];
    const uint32_t sb = smem_u32(s);
    const int t = threadIdx.x;
    const int warp = t >> 5, lane = t & 31;
    const int wm = warp >> 1, wn = warp & 1;
    const int b0r = blockIdx.y * TM;
    const int n0  = blockIdx.x * TN;

    float accL[2][4][4] = {}, accR[2][4][4] = {};

    auto load_stage = [&](int st) {
        const uint32_t base = sb + (uint32_t)((st & 1) * ST_SZ * 4);
        const int k0 = st * KC;
#pragma unroll
        for (int u = 0; u < 4; ++u) {                   // A: 1024 chunks
            int idx = t + 256 * u;
            int row = idx >> 3, c4 = idx & 7;
            cp16(base + (uint32_t)((ST_A + row * PIT + c4 * 4) * 4),
                 g_a + (size_t)(b0r + row) * C + k0 + c4 * 4);
        }
#pragma unroll
        for (int u = 0; u < 2; ++u) {                   // WL/WR: 512 each
            int idx = t + 256 * u;
            int row = idx >> 3, c4 = idx & 7;
            cp16(base + (uint32_t)((ST_WL + row * PIT + c4 * 4) * 4),
                 g_wl + (size_t)(n0 + row) * C + k0 + c4 * 4);
            cp16(base + (uint32_t)((ST_WR + row * PIT + c4 * 4) * 4),
                 g_wr + (size_t)(n0 + row) * C + k0 + c4 * 4);
        }
        cp_commit();
    };

    auto compute = [&](int buf) {
        const float* base = s + buf * ST_SZ;
        const float* Ab = base + ST_A  + (wm * 32 + (lane >> 2)) * PIT + (lane & 3);
        const float* Lb = base + ST_WL + (wn * 32 + (lane >> 2)) * PIT + (lane & 3);
        const float* Rb = base + ST_WR + (wn * 32 + (lane >> 2)) * PIT + (lane & 3);
#pragma unroll
        for (int kk = 0; kk < KC; kk += 8) {
            uint32_t a[2][4];
#pragma unroll
            for (int rf = 0; rf < 2; ++rf) {
                const float* ap = Ab + rf * 16 * PIT + kk;
                a[rf][0] = __float_as_uint(ap[0]);
                a[rf][1] = __float_as_uint(ap[8 * PIT]);
                a[rf][2] = __float_as_uint(ap[4]);
                a[rf][3] = __float_as_uint(ap[8 * PIT + 4]);
            }
#pragma unroll
            for (int cf = 0; cf < 4; ++cf) {
                const float* lp = Lb + cf * 8 * PIT + kk;
                const float* rp = Rb + cf * 8 * PIT + kk;
                uint32_t l0 = __float_as_uint(lp[0]), l1 = __float_as_uint(lp[4]);
                uint32_t r0 = __float_as_uint(rp[0]), r1 = __float_as_uint(rp[4]);
                mma8(accL[0][cf], a[0], l0, l1);
                mma8(accL[1][cf], a[1], l0, l1);
                mma8(accR[0][cf], a[0], r0, r1);
                mma8(accR[1][cf], a[1], r0, r1);
            }
        }
    };

    load_stage(0);
    load_stage(1);
#pragma unroll 1
    for (int it = 0; it < NIT; ++it) {
        const int buf = it & 1;
        if (it >= NIT - 2) cp_wait0(); else cp_wait1();
        __syncthreads();
        compute(buf);
        __syncthreads();
        if (it + 2 < NIT) load_stage(it + 2);
    }

    // epilogue: accumulators -> smem [128][EPI_P] x2 (reuses pipe smem)
    float* Ls = s;
    float* Rs = s + 128 * EPI_P;
#pragma unroll
    for (int rf = 0; rf < 2; ++rf)
#pragma unroll
        for (int cf = 0; cf < 4; ++cf) {
            const int r = wm * 32 + rf * 16 + (lane >> 2);
            const int c = wn * 32 + cf * 8 + 2 * (lane & 3);
            Ls[r * EPI_P + c]           = accL[rf][cf][0];
            Ls[r * EPI_P + c + 1]       = accL[rf][cf][1];
            Ls[(r + 8) * EPI_P + c]     = accL[rf][cf][2];
            Ls[(r + 8) * EPI_P + c + 1] = accL[rf][cf][3];
            Rs[r * EPI_P + c]           = accR[rf][cf][0];
            Rs[r * EPI_P + c + 1]       = accR[rf][cf][1];
            Rs[(r + 8) * EPI_P + c]     = accR[rf][cf][2];
            Rs[(r + 8) * EPI_P + c + 1] = accR[rf][cf][3];
        }
    __syncthreads();

    // bias + geometric product (Cl(3,0)) + tf32 round -> g_gp
#pragma unroll
    for (int j = 0; j < 4; ++j) {
        const int p = t + 256 * j;          // 1024 (b,c) pairs
        const int b = p >> 6, c = p & 63;
        float L[8], R[8];
#pragma unroll
        for (int i = 0; i < 8; ++i) {
            L[i] = Ls[(b * 8 + i) * EPI_P + c];
            R[i] = Rs[(b * 8 + i) * EPI_P + c];
        }
        L[0] += bLp[n0 + c];
        R[0] += bRp[n0 + c];
        float g[8];
        g[0] = L[0]*R[0] + L[1]*R[1] + L[2]*R[2] + L[3]*R[3] - L[4]*R[4] - L[5]*R[5] - L[6]*R[6] - L[7]*R[7];
        g[1] = L[1]*R[0] + L[0]*R[1] - L[2]*R[4] - L[3]*R[5] + L[4]*R[2] + L[5]*R[3] - L[6]*R[7] - L[7]*R[6];
        g[2] = L[0]*R[2] + L[2]*R[0] + L[1]*R[4] - L[4]*R[1] - L[3]*R[6] + L[6]*R[3] + L[5]*R[7] + L[7]*R[5];
        g[3] = L[0]*R[3] + L[3]*R[0] + L[1]*R[5] - L[5]*R[1] + L[2]*R[6] - L[6]*R[2] - L[4]*R[7] - L[7]*R[4];
        g[4] = L[0]*R[4] + L[4]*R[0] + L[1]*R[2] - L[2]*R[1] + L[3]*R[7] + L[7]*R[3] - L[5]*R[6] + L[6]*R[5];
        g[5] = L[0]*R[5] + L[5]*R[0] + L[1]*R[3] - L[3]*R[1] - L[2]*R[7] - L[7]*R[2] + L[4]*R[6] - L[6]*R[4];
        g[6] = L[0]*R[6] + L[6]*R[0] + L[2]*R[3] - L[3]*R[2] + L[1]*R[7] + L[7]*R[1] - L[4]*R[5] + L[5]*R[4];
        g[7] = L[0]*R[7] + L[7]*R[0] + L[1]*R[6] + L[6]*R[1] - L[2]*R[5] - L[5]*R[2] + L[3]*R[4] + L[4]*R[3];
#pragma unroll
        for (int i = 0; i < 8; ++i)
            g_gp[(size_t)(b0r + b * 8 + i) * C + n0 + c] = tfround(g[i]);
    }
}

// ============================================================================
// k2: O = gp @ WO^T + bias; store out (b,n,i); norm partials
// grid (NTILE, B/16): x = n-tile (fast), y = row-tile.
// ============================================================================
__global__ void __launch_bounds__(256) k2(
    const float* __restrict__ bOp, float* __restrict__ outp)
{
    extern __shared__ float s[];
    const uint32_t sb = smem_u32(s);
    const int t = threadIdx.x;
    const int warp = t >> 5, lane = t & 31;
    const int wm = warp >> 1, wn = warp & 1;
    const int b0r = blockIdx.y * TM;
    const int b0b = blockIdx.y * 16;
    const int n0  = blockIdx.x * TN;

    float acc[2][4][4] = {};

    auto load_stage = [&](int st) {
        const uint32_t base = sb + (uint32_t)((st & 1) * K2_ST_SZ * 4);
        const int k0 = st * KC;
#pragma unroll
        for (int u = 0; u < 4; ++u) {
            int idx = t + 256 * u;
            int row = idx >> 3, c4 = idx & 7;
            cp16(base + (uint32_t)((ST_A + row * PIT + c4 * 4) * 4),
                 g_gp + (size_t)(b0r + row) * C + k0 + c4 * 4);
        }
#pragma unroll
        for (int u = 0; u < 2; ++u) {
            int idx = t + 256 * u;
            int row = idx >> 3, c4 = idx & 7;
            cp16(base + (uint32_t)((ST_WL + row * PIT + c4 * 4) * 4),
                 g_wo + (size_t)(n0 + row) * C + k0 + c4 * 4);
        }
        cp_commit();
    };

    auto compute = [&](int buf) {
        const float* base = s + buf * K2_ST_SZ;
        const float* Ab = base + ST_A  + (wm * 32 + (lane >> 2)) * PIT + (lane & 3);
        const float* Wb = base + ST_WL + (wn * 32 + (lane >> 2)) * PIT + (lane & 3);
#pragma unroll
        for (int kk = 0; kk < KC; kk += 8) {
            uint32_t a[2][4];
#pragma unroll
            for (int rf = 0; rf < 2; ++rf) {
                const float* ap = Ab + rf * 16 * PIT + kk;
                a[rf][0] = __float_as_uint(ap[0]);
                a[rf][1] = __float_as_uint(ap[8 * PIT]);
                a[rf][2] = __float_as_uint(ap[4]);
                a[rf][3] = __float_as_uint(ap[8 * PIT + 4]);
            }
#pragma unroll
            for (int cf = 0; cf < 4; ++cf) {
                const float* wp = Wb + cf * 8 * PIT + kk;
                uint32_t w0 = __float_as_uint(wp[0]), w1 = __float_as_uint(wp[4]);
                mma8(acc[0][cf], a[0], w0, w1);
                mma8(acc[1][cf], a[1], w0, w1);
            }
        }
    };

    load_stage(0);
    load_stage(1);
#pragma unroll 1
    for (int it = 0; it < NIT; ++it) {
        const int buf = it & 1;
        if (it >= NIT - 2) cp_wait0(); else cp_wait1();
        __syncthreads();
        compute(buf);
        __syncthreads();
        if (it + 2 < NIT) load_stage(it + 2);
    }

    float* Os = s;                    // [128][EPI_P]
    float* Ns = s + 128 * EPI_P;      // [16][64]
#pragma unroll
    for (int rf = 0; rf < 2; ++rf)
#pragma unroll
        for (int cf = 0; cf < 4; ++cf) {
            const int r = wm * 32 + rf * 16 + (lane >> 2);
            const int c = wn * 32 + cf * 8 + 2 * (lane & 3);
            Os[r * EPI_P + c]           = acc[rf][cf][0];
            Os[r * EPI_P + c + 1]       = acc[rf][cf][1];
            Os[(r + 8) * EPI_P + c]     = acc[rf][cf][2];
            Os[(r + 8) * EPI_P + c + 1] = acc[rf][cf][3];
        }
    __syncthreads();

#pragma unroll
    for (int j = 0; j < 4; ++j) {
        const int p = t + 256 * j;
        const int b = p >> 6, c = p & 63;
        const int nc = n0 + c;
        float o[8];
#pragma unroll
        for (int i = 0; i < 8; ++i) o[i] = Os[(b * 8 + i) * EPI_P + c];
        o[0] += bOp[nc];
        float ss = 0.f;
#pragma unroll
        for (int i = 0; i < 8; ++i) ss += o[i] * o[i];
        Ns[b * 64 + c] = sqrtf(ss);
        float* dst = outp + ((size_t)(b0b + b) * C + nc) * NB;
        *reinterpret_cast<float4*>(dst)     = make_float4(o[0], o[1], o[2], o[3]);
        *reinterpret_cast<float4*>(dst + 4) = make_float4(o[4], o[5], o[6], o[7]);
    }
    __syncthreads();

    // norm reduce: warp w -> batches 2w, 2w+1
#pragma unroll
    for (int bb = 0; bb < 2; ++bb) {
        const int b = warp * 2 + bb;
        float v = Ns[b * 64 + lane] + Ns[b * 64 + lane + 32];
#pragma unroll
        for (int off = 16; off > 0; off >>= 1)
            v += __shfl_down_sync(0xffffffffu, v, off);
        if (lane == 0)
            g_normp[(size_t)(b0b + b) * NTILE + blockIdx.x] = v;
    }
}

// ============================================================================
__global__ void __launch_bounds__(256) k_red(int B) {
    const int b = blockIdx.x * 256 + threadIdx.x;
    if (b < B) {
        float v = 0.f;
#pragma unroll
        for (int j = 0; j < NTILE; ++j) v += g_normp[(size_t)b * NTILE + j];
        g_scale[b] = 1.f / (v * (1.f / (float)C) + 1e-6f);
    }
}

__global__ void __launch_bounds__(256) k_scale(float* __restrict__ outp,
                                               const float* __restrict__ an) {
    const size_t idx = (size_t)blockIdx.x * 256 + threadIdx.x;  // float4 index
    const int b = (int)(idx >> 10);
    const int c = ((int)idx >> 1) & (C - 1);
    const float v = an[c] * g_scale[b];
    float4* o4 = reinterpret_cast<float4*>(outp) + idx;
    float4 w = *o4;
    w.x *= v; w.y *= v; w.z *= v; w.w *= v;
    *o4 = w;
}

// ============================================================================
extern "C" void kernel_launch(void* const* d_in, const int* in_sizes, int n_in,
                              void* d_out, int out_size) {
    const float* vec1 = (const float*)d_in[0];
    const float* WL   = (const float*)d_in[1];
    const float* bL   = (const float*)d_in[2];
    const float* WR   = (const float*)d_in[3];
    const float* bR   = (const float*)d_in[4];
    const float* WO   = (const float*)d_in[5];
    const float* bO   = (const float*)d_in[6];
    const float* an   = (const float*)d_in[7];
    float* out = (float*)d_out;

    int B = in_sizes[0] / (C * NB);   // 16384
    if (B > MAXB) B = MAXB;

    cudaFuncSetAttribute(k1, cudaFuncAttributeMaxDynamicSharedMemorySize, K1_SMEM);
    cudaFuncSetAttribute(k2, cudaFuncAttributeMaxDynamicSharedMemorySize, K2_SMEM);

    k_wround<<<768, 256>>>(WL, WR, WO);
    k_tr<<<B, 256>>>(vec1);
    dim3 g(NTILE, B / 16);            // x = n-tile (fast) -> A tiles L2-resident
    k1<<<g, 256, K1_SMEM>>>(bL, bR);
    k2<<<g, 256, K2_SMEM>>>(bO, out);
    k_red<<<(B + 255) / 256, 256>>>(B);
    k_scale<<<(unsigned)((size_t)B * 1024 / 256), 256>>>(out, an);
}